// round 15
// baseline (speedup 1.0000x reference)
#include <cuda_runtime.h>
#include <cuda_fp16.h>
#include <cstdint>

#define NODES 25000
#define EDGES 150000
#define DIM   512
#define NKVQ  1536
#define HEADS 8
#define HALF1 12500
#define HALF2 (NODES - HALF1)

// ---------------- scratch (device globals) ----------------
__device__ __align__(256) __half g_WT[4 * DIM * DIM];   // 0=Wk,1=Wv,2=Wq,3=Wff
__device__ __align__(256) __half g_KVQ[NODES * NKVQ];   // [node][K|V|Q] fp16
__device__ __align__(256) __half g_GF[NODES * DIM];     // agg fp16
__device__ __align__(256) float  g_bias[NKVQ];          // [bk|bv|bq]
// CSR
__device__ __align__(16) int g_cnt[NODES + 1];
__device__ int g_fill[NODES];
__device__ int g_esend[EDGES];

// =================== helpers ===================
__device__ __forceinline__ uint32_t smem_u32(const void* p) {
    uint32_t a;
    asm("{ .reg .u64 t; cvta.to.shared.u64 t, %1; cvt.u32.u64 %0, t; }"
        : "=r"(a) : "l"(p));
    return a;
}

#define CP_ASYNC(dst, src, sz) \
    asm volatile("cp.async.cg.shared.global [%0], [%1], 16, %2;" \
                 :: "r"(dst), "l"(src), "r"(sz) : "memory")
#define CP_COMMIT() asm volatile("cp.async.commit_group;" ::: "memory")
#define CP_WAIT(n)  asm volatile("cp.async.wait_group %0;" :: "n"(n) : "memory")

#define LDMATRIX_X4(r0, r1, r2, r3, a) \
    asm volatile("ldmatrix.sync.aligned.m8n8.x4.shared.b16 {%0,%1,%2,%3}, [%4];" \
                 : "=r"(r0), "=r"(r1), "=r"(r2), "=r"(r3) : "r"(a))

#define MMA_F16(d, a0, a1, a2, a3, b0, b1)                                    \
    asm volatile("mma.sync.aligned.m16n8k16.row.col.f32.f16.f16.f32 "         \
                 "{%0,%1,%2,%3}, {%4,%5,%6,%7}, {%8,%9}, {%0,%1,%2,%3};"      \
                 : "+f"((d)[0]), "+f"((d)[1]), "+f"((d)[2]), "+f"((d)[3])     \
                 : "r"(a0), "r"(a1), "r"(a2), "r"(a3), "r"(b0), "r"(b1))

__device__ __forceinline__ uint32_t f2h2(float lo, float hi) {
    __half2 h = __floats2half2_rn(lo, hi);
    return *reinterpret_cast<uint32_t*>(&h);
}

// =================== common GEMM geometry ===================
#define BM 128
#define BN 256
#define BK 32
#define KCHUNKS (DIM / BK)
#define PITCH 80                       // fp16 tile row bytes
#define SZ_BT (256 * PITCH)            // 20480

// ---------- variant 1: fp16 A (FF path), 6 stages ----------
#define SZ_AT (128 * PITCH)            // 10240
#define STAGE16 (SZ_AT + SZ_BT)        // 30720
#define NST16 6
#define SMEM_G16 (NST16 * STAGE16)     // 184320

__global__ void __launch_bounds__(256, 1) gemm_f16(
    const __half* __restrict__ A, const __half* __restrict__ B,
    const float* __restrict__ bias, float* __restrict__ C, int M, int ldc)
{
    extern __shared__ char smem[];
    const uint32_t sb = smem_u32(smem);
    const int tid = threadIdx.x, wid = tid >> 5, lane = tid & 31;
    const int warpRow = wid & 1, warpCol = wid >> 1;
    const int rowBase = blockIdx.y * BM;
    const int nBase = blockIdx.x * BN;

    const int ar0 = tid >> 1, ak0 = (tid & 1) * 2;
    const uint32_t soA0 = (uint32_t)(ar0 * PITCH + ak0 * 16);
    const uint32_t soA1 = soA0 + 16;
    const uint32_t szA  = (rowBase + ar0 < M) ? 16u : 0u;
    const size_t gA0 = (size_t)(rowBase + ar0) * DIM + ak0 * 8;
    const size_t gA1 = gA0 + 8;

    uint32_t soB[4]; size_t gB[4];
#pragma unroll
    for (int i = 0; i < 4; i++) {
        int idx = i * 256 + tid;
        int br = idx >> 2, bk4 = idx & 3;
        soB[i] = (uint32_t)(br * PITCH + bk4 * 16);
        gB[i] = (size_t)(nBase + br) * DIM + bk4 * 8;
    }

    const uint32_t aOff = (uint32_t)((warpRow * 64 + (lane & 7) + ((lane >> 3) & 1) * 8) * PITCH
                                     + (lane >> 4) * 16);
    const uint32_t bOff = (uint32_t)((warpCol * 64 + (lane >> 4) * 8 + (lane & 7)) * PITCH
                                     + ((lane >> 3) & 1) * 16);

    float acc[4][8][4];
#pragma unroll
    for (int f = 0; f < 4; f++)
#pragma unroll
        for (int g = 0; g < 8; g++)
#pragma unroll
            for (int i = 0; i < 4; i++) acc[f][g][i] = 0.0f;

    auto load_stage = [&](int chunk, int buf) {
        const int k0 = chunk * BK;
        const uint32_t st = sb + (uint32_t)buf * STAGE16;
        CP_ASYNC(st + soA0, A + gA0 + k0, szA);
        CP_ASYNC(st + soA1, A + gA1 + k0, szA);
#pragma unroll
        for (int i = 0; i < 4; i++)
            CP_ASYNC(st + SZ_AT + soB[i], B + gB[i] + k0, 16u);
        CP_COMMIT();
    };

#pragma unroll
    for (int s = 0; s < NST16 - 1; s++) load_stage(s, s);

    int buf = 0;
    for (int c = 0; c < KCHUNKS; c++) {
        int n = KCHUNKS - 1 - c; if (n > NST16 - 2) n = NST16 - 2;
        switch (n) {
            case 0: CP_WAIT(0); break;
            case 1: CP_WAIT(1); break;
            case 2: CP_WAIT(2); break;
            case 3: CP_WAIT(3); break;
            default: CP_WAIT(4); break;
        }
        __syncthreads();

        if (c + NST16 - 1 < KCHUNKS) {
            int nb = buf + NST16 - 1; if (nb >= NST16) nb -= NST16;
            load_stage(c + NST16 - 1, nb);
        }

        const uint32_t st = sb + (uint32_t)buf * STAGE16;
#pragma unroll
        for (int ks = 0; ks < 2; ks++) {
            const uint32_t kb = (uint32_t)(ks * 32);
            uint32_t aF[4][4], bF[8][2];
#pragma unroll
            for (int f = 0; f < 4; f++)
                LDMATRIX_X4(aF[f][0], aF[f][1], aF[f][2], aF[f][3],
                            st + aOff + (uint32_t)(f * 16 * PITCH) + kb);
#pragma unroll
            for (int p = 0; p < 4; p++)
                LDMATRIX_X4(bF[2 * p][0], bF[2 * p][1], bF[2 * p + 1][0], bF[2 * p + 1][1],
                            st + SZ_AT + bOff + (uint32_t)(p * 16 * PITCH) + kb);
#pragma unroll
            for (int f = 0; f < 4; f++)
#pragma unroll
                for (int g = 0; g < 8; g++)
                    MMA_F16(acc[f][g], aF[f][0], aF[f][1], aF[f][2], aF[f][3],
                            bF[g][0], bF[g][1]);
        }
        buf++; if (buf >= NST16) buf -= NST16;
    }

#pragma unroll
    for (int f = 0; f < 4; f++) {
        const int r0 = rowBase + warpRow * 64 + f * 16 + (lane >> 2);
#pragma unroll
        for (int g = 0; g < 8; g++) {
            const int col = nBase + warpCol * 64 + g * 8 + (lane & 3) * 2;
            const float2 b = *(const float2*)(bias + col);
            if (r0 < M)
                *(float2*)(C + (size_t)r0 * ldc + col) =
                    make_float2(acc[f][g][0] + b.x, acc[f][g][1] + b.y);
            if (r0 + 8 < M)
                *(float2*)(C + (size_t)(r0 + 8) * ldc + col) =
                    make_float2(acc[f][g][2] + b.x, acc[f][g][3] + b.y);
        }
    }
}

// ---------- variant 2: fp32 A consumed directly (KVQ path), 5 stages -------
#define PITCH_A32 144                  // 32 floats (128B) + 16B pad
#define SZ_A32 (128 * PITCH_A32)       // 18432
#define STAGE32 (SZ_A32 + SZ_BT)       // 38912
#define NST32 5
#define SMEM_G32 (NST32 * STAGE32)     // 194560

__global__ void __launch_bounds__(256, 1) gemm_a32(
    const float* __restrict__ A, const __half* __restrict__ B,
    const float* __restrict__ bias, __half* __restrict__ C, int M, int ldc)
{
    extern __shared__ char smem[];
    const uint32_t sb = smem_u32(smem);
    const int tid = threadIdx.x, wid = tid >> 5, lane = tid & 31;
    const int warpRow = wid & 1, warpCol = wid >> 1;
    const int rowBase = blockIdx.y * BM;
    const int nBase = blockIdx.x * BN;

    // A fp32: 128 rows x 128B data per row -> 1024 chunks of 16B, 4/thread
    uint32_t soA[4]; size_t gA[4]; uint32_t szA[4];
#pragma unroll
    for (int i = 0; i < 4; i++) {
        int c = i * 256 + tid;
        int row = c >> 3, ch = c & 7;
        soA[i] = (uint32_t)(row * PITCH_A32 + ch * 16);
        gA[i] = (size_t)(rowBase + row) * DIM + ch * 4;
        szA[i] = (rowBase + row < M) ? 16u : 0u;
    }
    uint32_t soB[4]; size_t gB[4];
#pragma unroll
    for (int i = 0; i < 4; i++) {
        int idx = i * 256 + tid;
        int br = idx >> 2, bk4 = idx & 3;
        soB[i] = (uint32_t)(br * PITCH + bk4 * 16);
        gB[i] = (size_t)(nBase + br) * DIM + bk4 * 8;
    }

    const uint32_t bOff = (uint32_t)((warpCol * 64 + (lane >> 4) * 8 + (lane & 7)) * PITCH
                                     + ((lane >> 3) & 1) * 16);
    // per-thread fp32 A fragment base (bytes into A tile)
    const uint32_t aBase = (uint32_t)((warpRow * 64 + (lane >> 2)) * PITCH_A32
                                      + (lane & 3) * 8);

    float acc[4][8][4];
#pragma unroll
    for (int f = 0; f < 4; f++)
#pragma unroll
        for (int g = 0; g < 8; g++)
#pragma unroll
            for (int i = 0; i < 4; i++) acc[f][g][i] = 0.0f;

    auto load_stage = [&](int chunk, int buf) {
        const int k0 = chunk * BK;
        const uint32_t st = sb + (uint32_t)buf * STAGE32;
#pragma unroll
        for (int i = 0; i < 4; i++)
            CP_ASYNC(st + soA[i], A + gA[i] + k0, szA[i]);
#pragma unroll
        for (int i = 0; i < 4; i++)
            CP_ASYNC(st + SZ_A32 + soB[i], B + gB[i] + k0, 16u);
        CP_COMMIT();
    };

#pragma unroll
    for (int s = 0; s < NST32 - 1; s++) load_stage(s, s);

    int buf = 0;
    for (int c = 0; c < KCHUNKS; c++) {
        int n = KCHUNKS - 1 - c; if (n > NST32 - 2) n = NST32 - 2;
        switch (n) {
            case 0: CP_WAIT(0); break;
            case 1: CP_WAIT(1); break;
            case 2: CP_WAIT(2); break;
            default: CP_WAIT(3); break;
        }
        __syncthreads();

        if (c + NST32 - 1 < KCHUNKS) {
            int nb = buf + NST32 - 1; if (nb >= NST32) nb -= NST32;
            load_stage(c + NST32 - 1, nb);
        }

        const char* stp = smem + (size_t)buf * STAGE32;
        const uint32_t st = sb + (uint32_t)buf * STAGE32;
#pragma unroll
        for (int ks = 0; ks < 2; ks++) {
            const uint32_t kb16 = (uint32_t)(ks * 32);   // B: 16 halves = 32B
            const uint32_t kb32 = (uint32_t)(ks * 64);   // A: 16 floats = 64B
            uint32_t aF[4][4], bF[8][2];
#pragma unroll
            for (int f = 0; f < 4; f++) {
                const char* ap = stp + aBase + (uint32_t)(f * 16 * PITCH_A32) + kb32;
                float2 v0 = *(const float2*)(ap);
                float2 v1 = *(const float2*)(ap + 8 * PITCH_A32);
                float2 v2 = *(const float2*)(ap + 32);
                float2 v3 = *(const float2*)(ap + 8 * PITCH_A32 + 32);
                aF[f][0] = f2h2(v0.x, v0.y);
                aF[f][1] = f2h2(v1.x, v1.y);
                aF[f][2] = f2h2(v2.x, v2.y);
                aF[f][3] = f2h2(v3.x, v3.y);
            }
#pragma unroll
            for (int p = 0; p < 4; p++)
                LDMATRIX_X4(bF[2 * p][0], bF[2 * p][1], bF[2 * p + 1][0], bF[2 * p + 1][1],
                            st + SZ_A32 + bOff + (uint32_t)(p * 16 * PITCH) + kb16);
#pragma unroll
            for (int f = 0; f < 4; f++)
#pragma unroll
                for (int g = 0; g < 8; g++)
                    MMA_F16(acc[f][g], aF[f][0], aF[f][1], aF[f][2], aF[f][3],
                            bF[g][0], bF[g][1]);
        }
        buf++; if (buf >= NST32) buf -= NST32;
    }

#pragma unroll
    for (int f = 0; f < 4; f++) {
        const int r0 = rowBase + warpRow * 64 + f * 16 + (lane >> 2);
#pragma unroll
        for (int g = 0; g < 8; g++) {
            const int col = nBase + warpCol * 64 + g * 8 + (lane & 3) * 2;
            const float2 b = *(const float2*)(bias + col);
            if (r0 < M)
                *(__half2*)(C + (size_t)r0 * ldc + col) =
                    __floats2half2_rn(acc[f][g][0] + b.x, acc[f][g][1] + b.y);
            if (r0 + 8 < M)
                *(__half2*)(C + (size_t)(r0 + 8) * ldc + col) =
                    __floats2half2_rn(acc[f][g][2] + b.x, acc[f][g][3] + b.y);
        }
    }
}

// ======== prep (stream0): 4x weight transpose + bias concat ========
#define CTA_TR 1024
#define CTA_MAIN (CTA_TR + 2)

__global__ void __launch_bounds__(256) prep_main(
    const float* __restrict__ wk, const float* __restrict__ wv,
    const float* __restrict__ wq, const float* __restrict__ wff,
    const float* __restrict__ bk, const float* __restrict__ bq,
    const float* __restrict__ bv)
{
    __shared__ float t[32][33];
    const int cta = blockIdx.x, tid = threadIdx.x;

    if (cta < CTA_TR) {
        const int z = cta >> 8, rem = cta & 255;
        const float* in = (z == 0) ? wk : (z == 1) ? wv : (z == 2) ? wq : wff;
        __half* oh = g_WT + (size_t)z * DIM * DIM;
        const int bx = (rem & 15) * 32, by = (rem >> 4) * 32;
        const int tx = tid & 31, ty = tid >> 5;
#pragma unroll
        for (int j = 0; j < 32; j += 8)
            t[ty + j][tx] = in[(size_t)(by + ty + j) * DIM + bx + tx];
        __syncthreads();
#pragma unroll
        for (int j = 0; j < 32; j += 8)
            oh[(size_t)(bx + ty + j) * DIM + by + tx] =
                __float2half_rn(t[tx][ty + j]);
    } else {
        int i = (cta - CTA_TR) * 256 + tid;
        if (i < DIM) {
            g_bias[i] = bk[i];
            g_bias[DIM + i] = bv[i];
            g_bias[2 * DIM + i] = bq[i];
        }
    }
}

// ======== prep (s2): zero CSR arrays ========
__global__ void prep_zero() {
    int i = blockIdx.x * blockDim.x + threadIdx.x;
    if (i <= NODES) g_cnt[i] = 0;
    if (i < NODES)  g_fill[i] = 0;
}

// =================== CSR build ===================
__global__ void hist_recv(const int* __restrict__ recv) {
    int e = blockIdx.x * blockDim.x + threadIdx.x;
    if (e < EDGES) atomicAdd(&g_cnt[recv[e] + 1], 1);
}

#define SC_T 1024
#define SC_V 7
__global__ void __launch_bounds__(SC_T) scan_offsets() {
    __shared__ int wsum[32];
    const int t = threadIdx.x, lane = t & 31, wid = t >> 5;
    const int base = t * (SC_V * 4);
    int v[SC_V * 4];
#pragma unroll
    for (int i = 0; i < SC_V; i++) {
        int idx = base + i * 4;
        if (idx + 3 <= NODES) {
            int4 u = *(const int4*)&g_cnt[idx];
            v[4 * i] = u.x; v[4 * i + 1] = u.y; v[4 * i + 2] = u.z; v[4 * i + 3] = u.w;
        } else {
#pragma unroll
            for (int k = 0; k < 4; k++) {
                int id = idx + k;
                v[4 * i + k] = (id <= NODES) ? g_cnt[id] : 0;
            }
        }
    }
#pragma unroll
    for (int i = 1; i < SC_V * 4; i++) v[i] += v[i - 1];
    const int mytot = v[SC_V * 4 - 1];
    int inc = mytot;
#pragma unroll
    for (int d = 1; d < 32; d <<= 1) {
        int n = __shfl_up_sync(0xffffffffu, inc, d);
        if (lane >= d) inc += n;
    }
    if (lane == 31) wsum[wid] = inc;
    __syncthreads();
    if (wid == 0) {
        int s = wsum[lane];
#pragma unroll
        for (int d = 1; d < 32; d <<= 1) {
            int n = __shfl_up_sync(0xffffffffu, s, d);
            if (lane >= d) s += n;
        }
        wsum[lane] = s;
    }
    __syncthreads();
    const int off = (wid > 0 ? wsum[wid - 1] : 0) + (inc - mytot);
#pragma unroll
    for (int i = 0; i < SC_V; i++) {
        int idx = base + i * 4;
        if (idx + 3 <= NODES) {
            int4 u = make_int4(v[4 * i] + off, v[4 * i + 1] + off,
                               v[4 * i + 2] + off, v[4 * i + 3] + off);
            *(int4*)&g_cnt[idx] = u;
        } else {
#pragma unroll
            for (int k = 0; k < 4; k++) {
                int id = idx + k;
                if (id <= NODES) g_cnt[id] = v[4 * i + k] + off;
            }
        }
    }
}

__global__ void scatter_csr(const int* __restrict__ send,
                            const int* __restrict__ recv) {
    int e = blockIdx.x * blockDim.x + threadIdx.x;
    if (e >= EDGES) return;
    int r = recv[e];
    int pos = g_cnt[r] + atomicAdd(&g_fill[r], 1);
    g_esend[pos] = send[e];
}

// =================== fused node attention + aggregation (R13 form) ==========
__device__ __forceinline__ void ld16h(const __half* p, float* f) {
    uint4 u0 = *(const uint4*)p;
    uint4 u1 = *(const uint4*)(p + 8);
    const __half2* h0 = (const __half2*)&u0;
    const __half2* h1 = (const __half2*)&u1;
#pragma unroll
    for (int i = 0; i < 4; i++) {
        float2 a = __half22float2(h0[i]);
        f[2 * i] = a.x; f[2 * i + 1] = a.y;
        float2 b = __half22float2(h1[i]);
        f[8 + 2 * i] = b.x; f[8 + 2 * i + 1] = b.y;
    }
}

__global__ void __launch_bounds__(256) node_attn_agg(int nodeBase, int nodeCnt) {
    int gw = (blockIdx.x * blockDim.x + threadIdx.x) >> 5;
    if (gw >= nodeCnt) return;
    const int lane = threadIdx.x & 31;
    const int r = nodeBase + gw;

    float q[16];
    ld16h(&g_KVQ[(size_t)r * NKVQ + 1024 + lane * 16], q);

    const int beg = g_cnt[r], end = g_cnt[r + 1];
    float denom = 0.0f;
    float a[16];
#pragma unroll
    for (int i = 0; i < 16; i++) a[i] = 0.0f;

    int j = beg;
    for (; j + 1 < end; j += 2) {
        int s0 = g_esend[j], s1 = g_esend[j + 1];
        const __half* b0 = &g_KVQ[(size_t)s0 * NKVQ + lane * 16];
        const __half* b1 = &g_KVQ[(size_t)s1 * NKVQ + lane * 16];
        float k0[16], v0[16], k1[16], v1[16];
        ld16h(b0, k0); ld16h(b1, k1);
        ld16h(b0 + 512, v0); ld16h(b1 + 512, v1);

        float d0 = 0.f, d1 = 0.f;
#pragma unroll
        for (int i = 0; i < 16; i++) { d0 += q[i] * k0[i]; d1 += q[i] * k1[i]; }
        d0 += __shfl_xor_sync(0xffffffffu, d0, 1);
        d1 += __shfl_xor_sync(0xffffffffu, d1, 1);
        d0 += __shfl_xor_sync(0xffffffffu, d0, 2);
        d1 += __shfl_xor_sync(0xffffffffu, d1, 2);
        float w0 = __expf(d0 * 0.125f);
        float w1 = __expf(d1 * 0.125f);
        denom += w0 + w1;
#pragma unroll
        for (int i = 0; i < 16; i++) a[i] += w0 * v0[i] + w1 * v1[i];
    }
    if (j < end) {
        int s = g_esend[j];
        const __half* b = &g_KVQ[(size_t)s * NKVQ + lane * 16];
        float k[16], v[16];
        ld16h(b, k); ld16h(b + 512, v);
        float d = 0.f;
#pragma unroll
        for (int i = 0; i < 16; i++) d += q[i] * k[i];
        d += __shfl_xor_sync(0xffffffffu, d, 1);
        d += __shfl_xor_sync(0xffffffffu, d, 2);
        float w = __expf(d * 0.125f);
        denom += w;
#pragma unroll
        for (int i = 0; i < 16; i++) a[i] += w * v[i];
    }

    float inv = (denom > 0.0f) ? 1.0f / denom : 0.0f;
    __half2 hp[8];
#pragma unroll
    for (int i = 0; i < 8; i++)
        hp[i] = __floats2half2_rn(a[2 * i] * inv, a[2 * i + 1] * inv);
    ((uint4*)&g_GF[(size_t)r * DIM + lane * 16])[0] = ((const uint4*)hp)[0];
    ((uint4*)&g_GF[(size_t)r * DIM + lane * 16])[1] = ((const uint4*)hp)[1];
}

// ---------------------------------------------------------------------------
extern "C" void kernel_launch(void* const* d_in, const int* in_sizes, int n_in,
                              void* d_out, int out_size) {
    const float* x   = (const float*)d_in[0];
    const int*  eidx = (const int*)  d_in[1];
    const float* Wk  = (const float*)d_in[2];
    const float* bk  = (const float*)d_in[3];
    const float* Wq  = (const float*)d_in[4];
    const float* bq  = (const float*)d_in[5];
    const float* Wv  = (const float*)d_in[6];
    const float* bv  = (const float*)d_in[7];
    const float* Wff = (const float*)d_in[8];
    const float* bff = (const float*)d_in[9];
    float* out = (float*)d_out;

    const int* send = eidx;
    const int* recv = eidx + EDGES;

    float* biasp;
    __half *GF, *KVQ, *WT;
    cudaGetSymbolAddress((void**)&biasp, g_bias);
    cudaGetSymbolAddress((void**)&GF,  g_GF);
    cudaGetSymbolAddress((void**)&KVQ, g_KVQ);
    cudaGetSymbolAddress((void**)&WT,  g_WT);

    cudaFuncSetAttribute((const void*)gemm_a32,
        cudaFuncAttributeMaxDynamicSharedMemorySize, SMEM_G32);
    cudaFuncSetAttribute((const void*)gemm_f16,
        cudaFuncAttributeMaxDynamicSharedMemorySize, SMEM_G16);

    static cudaStream_t s2 = nullptr;
    static cudaEvent_t evFork = nullptr, evJoin = nullptr, evA0 = nullptr,
                       evF0 = nullptr;
    if (s2 == nullptr) {
        cudaStreamCreateWithFlags(&s2, cudaStreamNonBlocking);
        cudaEventCreateWithFlags(&evFork, cudaEventDisableTiming);
        cudaEventCreateWithFlags(&evJoin, cudaEventDisableTiming);
        cudaEventCreateWithFlags(&evA0, cudaEventDisableTiming);
        cudaEventCreateWithFlags(&evF0, cudaEventDisableTiming);
    }

    // fork: CSR chain on s2 (independent of stream0 work)
    cudaEventRecord(evFork, 0);
    cudaStreamWaitEvent(s2, evFork, 0);
    prep_zero<<<(NODES + 256) / 256, 256, 0, s2>>>();
    hist_recv<<<(EDGES + 255) / 256, 256, 0, s2>>>(recv);
    scan_offsets<<<1, SC_T, 0, s2>>>();
    scatter_csr<<<(EDGES + 255) / 256, 256, 0, s2>>>(send, recv);
    cudaEventRecord(evJoin, s2);

    // stream0: prep (transposes + bias), then KVQ GEMM on raw fp32 x
    prep_main<<<CTA_MAIN, 256>>>(Wk, Wv, Wq, Wff, bk, bq, bv);
    dim3 gkvq(NKVQ / BN, (NODES + BM - 1) / BM);   // (6, 196)
    gemm_a32<<<gkvq, 256, SMEM_G32>>>(x, WT, biasp, KVQ, NODES, NKVQ);

    // join: attention needs GEMM (stream0 order) + CSR (event)
    cudaStreamWaitEvent(0, evJoin, 0);

    // pipelined attention + FF over node halves
    node_attn_agg<<<(HALF1 * 32 + 255) / 256, 256>>>(0, HALF1);
    cudaEventRecord(evA0, 0);
    node_attn_agg<<<(HALF2 * 32 + 255) / 256, 256>>>(HALF1, HALF2);

    cudaStreamWaitEvent(s2, evA0, 0);
    dim3 gff0(DIM / BN, (HALF1 + BM - 1) / BM);    // (2, 98)
    gemm_f16<<<gff0, 256, SMEM_G16, s2>>>(GF, WT + 3 * DIM * DIM, bff,
                                          out, HALF1, DIM);
    cudaEventRecord(evF0, s2);

    dim3 gff1(DIM / BN, (HALF2 + BM - 1) / BM);    // (2, 98)
    gemm_f16<<<gff1, 256, SMEM_G16>>>(GF + (size_t)HALF1 * DIM,
                                      WT + 3 * DIM * DIM, bff,
                                      out + (size_t)HALF1 * DIM,
                                      HALF2, DIM);
    cudaStreamWaitEvent(0, evF0, 0);
}

// round 16
// speedup vs baseline: 1.0661x; 1.0661x over previous
#include <cuda_runtime.h>
#include <cuda_fp16.h>
#include <cstdint>

#define NODES 25000
#define EDGES 150000
#define DIM   512
#define NKVQ  1536
#define HEADS 8
#define HALF1 12500
#define HALF2 (NODES - HALF1)

// ---------------- scratch (device globals) ----------------
// weight slots (transposed [N][K] fp16): 0=Wk, 1=Wv, 2=Wq, 3=Wff
__device__ __align__(256) __half g_WT[4 * DIM * DIM];
__device__ __align__(256) __half g_KVQ[NODES * NKVQ];   // [node][K|V|Q] fp16
__device__ __align__(256) __half g_XF[NODES * DIM];     // x as fp16
__device__ __align__(256) __half g_GF[NODES * DIM];     // agg as fp16
__device__ __align__(256) float  g_bias[NKVQ];          // [bk|bv|bq]
// CSR
__device__ __align__(16) int g_cnt[NODES + 1];
__device__ int g_fill[NODES];
__device__ int g_esend[EDGES];

// =================== helpers ===================
__device__ __forceinline__ uint32_t smem_u32(const void* p) {
    uint32_t a;
    asm("{ .reg .u64 t; cvta.to.shared.u64 t, %1; cvt.u32.u64 %0, t; }"
        : "=r"(a) : "l"(p));
    return a;
}

#define CP_ASYNC(dst, src, sz) \
    asm volatile("cp.async.cg.shared.global [%0], [%1], 16, %2;" \
                 :: "r"(dst), "l"(src), "r"(sz) : "memory")
#define CP_COMMIT() asm volatile("cp.async.commit_group;" ::: "memory")
#define CP_WAIT(n)  asm volatile("cp.async.wait_group %0;" :: "n"(n) : "memory")

#define LDMATRIX_X4(r0, r1, r2, r3, a) \
    asm volatile("ldmatrix.sync.aligned.m8n8.x4.shared.b16 {%0,%1,%2,%3}, [%4];" \
                 : "=r"(r0), "=r"(r1), "=r"(r2), "=r"(r3) : "r"(a))

#define MMA_F16(d, a0, a1, a2, a3, b0, b1)                                    \
    asm volatile("mma.sync.aligned.m16n8k16.row.col.f32.f16.f16.f32 "         \
                 "{%0,%1,%2,%3}, {%4,%5,%6,%7}, {%8,%9}, {%0,%1,%2,%3};"      \
                 : "+f"((d)[0]), "+f"((d)[1]), "+f"((d)[2]), "+f"((d)[3])     \
                 : "r"(a0), "r"(a1), "r"(a2), "r"(a3), "r"(b0), "r"(b1))

// =================== fp16 GEMM (single weight term) =========================
// C[M,N] = A_f16[M,512] @ B^T + bias. CTA 128x256, 8 warps, BK=32, 6 stages.
#define BM 128
#define BN 256
#define BK 32
#define KCHUNKS (DIM / BK)
#define PITCH 80
#define SZ_AT (128 * PITCH)            // 10240
#define SZ_BT (256 * PITCH)            // 20480
#define STAGE (SZ_AT + SZ_BT)          // 30720
#define NST 6
#define SMEM_G (NST * STAGE)           // 184320

template <bool HOUT>
__global__ void __launch_bounds__(256, 1) gemm_f16(
    const __half* __restrict__ A, const __half* __restrict__ B,
    const float* __restrict__ bias, void* __restrict__ Cv, int M, int ldc)
{
    extern __shared__ char smem[];
    const uint32_t sb = smem_u32(smem);
    const int tid = threadIdx.x, wid = tid >> 5, lane = tid & 31;
    const int warpRow = wid & 1, warpCol = wid >> 1;
    const int rowBase = blockIdx.y * BM;
    const int nBase = blockIdx.x * BN;

    const int ar0 = tid >> 1, ak0 = (tid & 1) * 2;
    const uint32_t soA0 = (uint32_t)(ar0 * PITCH + ak0 * 16);
    const uint32_t soA1 = soA0 + 16;
    const uint32_t szA  = (rowBase + ar0 < M) ? 16u : 0u;
    const size_t gA0 = (size_t)(rowBase + ar0) * DIM + ak0 * 8;
    const size_t gA1 = gA0 + 8;

    uint32_t soB[4]; size_t gB[4];
#pragma unroll
    for (int i = 0; i < 4; i++) {
        int idx = i * 256 + tid;
        int br = idx >> 2, bk4 = idx & 3;
        soB[i] = (uint32_t)(br * PITCH + bk4 * 16);
        gB[i] = (size_t)(nBase + br) * DIM + bk4 * 8;
    }

    const uint32_t aOff = (uint32_t)((warpRow * 64 + (lane & 7) + ((lane >> 3) & 1) * 8) * PITCH
                                     + (lane >> 4) * 16);
    const uint32_t bOff = (uint32_t)((warpCol * 64 + (lane >> 4) * 8 + (lane & 7)) * PITCH
                                     + ((lane >> 3) & 1) * 16);

    float acc[4][8][4];
#pragma unroll
    for (int f = 0; f < 4; f++)
#pragma unroll
        for (int g = 0; g < 8; g++)
#pragma unroll
            for (int i = 0; i < 4; i++) acc[f][g][i] = 0.0f;

    auto load_stage = [&](int chunk, int buf) {
        const int k0 = chunk * BK;
        const uint32_t st = sb + (uint32_t)buf * STAGE;
        CP_ASYNC(st + soA0, A + gA0 + k0, szA);
        CP_ASYNC(st + soA1, A + gA1 + k0, szA);
#pragma unroll
        for (int i = 0; i < 4; i++)
            CP_ASYNC(st + SZ_AT + soB[i], B + gB[i] + k0, 16u);
        CP_COMMIT();
    };

#pragma unroll
    for (int s = 0; s < NST - 1; s++) load_stage(s, s);

    int buf = 0;
    for (int c = 0; c < KCHUNKS; c++) {
        int n = KCHUNKS - 1 - c; if (n > NST - 2) n = NST - 2;
        switch (n) {
            case 0: CP_WAIT(0); break;
            case 1: CP_WAIT(1); break;
            case 2: CP_WAIT(2); break;
            case 3: CP_WAIT(3); break;
            default: CP_WAIT(4); break;
        }
        __syncthreads();

        if (c + NST - 1 < KCHUNKS) {
            int nb = buf + NST - 1; if (nb >= NST) nb -= NST;
            load_stage(c + NST - 1, nb);
        }

        const uint32_t st = sb + (uint32_t)buf * STAGE;
#pragma unroll
        for (int ks = 0; ks < 2; ks++) {
            const uint32_t kb = (uint32_t)(ks * 32);
            uint32_t aF[4][4], bF[8][2];
#pragma unroll
            for (int f = 0; f < 4; f++)
                LDMATRIX_X4(aF[f][0], aF[f][1], aF[f][2], aF[f][3],
                            st + aOff + (uint32_t)(f * 16 * PITCH) + kb);
#pragma unroll
            for (int p = 0; p < 4; p++)
                LDMATRIX_X4(bF[2 * p][0], bF[2 * p][1], bF[2 * p + 1][0], bF[2 * p + 1][1],
                            st + SZ_AT + bOff + (uint32_t)(p * 16 * PITCH) + kb);
#pragma unroll
            for (int f = 0; f < 4; f++)
#pragma unroll
                for (int g = 0; g < 8; g++)
                    MMA_F16(acc[f][g], aF[f][0], aF[f][1], aF[f][2], aF[f][3],
                            bF[g][0], bF[g][1]);
        }
        buf++; if (buf >= NST) buf -= NST;
    }

#pragma unroll
    for (int f = 0; f < 4; f++) {
        const int r0 = rowBase + warpRow * 64 + f * 16 + (lane >> 2);
#pragma unroll
        for (int g = 0; g < 8; g++) {
            const int col = nBase + warpCol * 64 + g * 8 + (lane & 3) * 2;
            const float2 b = *(const float2*)(bias + col);
            if (HOUT) {
                __half* Cp = (__half*)Cv;
                if (r0 < M)
                    *(__half2*)(Cp + (size_t)r0 * ldc + col) =
                        __floats2half2_rn(acc[f][g][0] + b.x, acc[f][g][1] + b.y);
                if (r0 + 8 < M)
                    *(__half2*)(Cp + (size_t)(r0 + 8) * ldc + col) =
                        __floats2half2_rn(acc[f][g][2] + b.x, acc[f][g][3] + b.y);
            } else {
                float* Cp = (float*)Cv;
                if (r0 < M)
                    *(float2*)(Cp + (size_t)r0 * ldc + col) =
                        make_float2(acc[f][g][0] + b.x, acc[f][g][1] + b.y);
                if (r0 + 8 < M)
                    *(float2*)(Cp + (size_t)(r0 + 8) * ldc + col) =
                        make_float2(acc[f][g][2] + b.x, acc[f][g][3] + b.y);
            }
        }
    }
}

// ======== fused prep: x cast + 4x weight transpose + csr zero + bias ========
// grid partition: [0,6250) cast | [6250,7274) transpose | [7274,7374) misc
#define CTA_CAST 6250
#define CTA_TR   1024
#define CTA_ALL  (CTA_CAST + CTA_TR + 100)

__global__ void __launch_bounds__(256) prep_all(
    const float* __restrict__ x,
    const float* __restrict__ wk, const float* __restrict__ wv,
    const float* __restrict__ wq, const float* __restrict__ wff,
    const float* __restrict__ bk, const float* __restrict__ bq,
    const float* __restrict__ bv)
{
    __shared__ float t[32][33];
    const int cta = blockIdx.x, tid = threadIdx.x;

    if (cta < CTA_CAST) {
        int i = cta * 256 + tid;
        float4 v0 = ((const float4*)x)[2 * i];
        float4 v1 = ((const float4*)x)[2 * i + 1];
        __half2 h[4];
        h[0] = __floats2half2_rn(v0.x, v0.y);
        h[1] = __floats2half2_rn(v0.z, v0.w);
        h[2] = __floats2half2_rn(v1.x, v1.y);
        h[3] = __floats2half2_rn(v1.z, v1.w);
        ((uint4*)g_XF)[i] = *(const uint4*)h;
    } else if (cta < CTA_CAST + CTA_TR) {
        const int tr = cta - CTA_CAST;
        const int z = tr >> 8, rem = tr & 255;
        const float* in = (z == 0) ? wk : (z == 1) ? wv : (z == 2) ? wq : wff;
        __half* oh = g_WT + (size_t)z * DIM * DIM;
        const int bx = (rem & 15) * 32, by = (rem >> 4) * 32;
        const int tx = tid & 31, ty = tid >> 5;
#pragma unroll
        for (int j = 0; j < 32; j += 8)
            t[ty + j][tx] = in[(size_t)(by + ty + j) * DIM + bx + tx];
        __syncthreads();
#pragma unroll
        for (int j = 0; j < 32; j += 8)
            oh[(size_t)(bx + ty + j) * DIM + by + tx] =
                __float2half_rn(t[tx][ty + j]);
    } else {
        int i = (cta - CTA_CAST - CTA_TR) * 256 + tid;
        if (i <= NODES) g_cnt[i] = 0;
        if (i < NODES)  g_fill[i] = 0;
        if (i < DIM) {
            g_bias[i] = bk[i];
            g_bias[DIM + i] = bv[i];
            g_bias[2 * DIM + i] = bq[i];
        }
    }
}

// =================== CSR build ===================
__global__ void hist_recv(const int* __restrict__ recv) {
    int e = blockIdx.x * blockDim.x + threadIdx.x;
    if (e < EDGES) atomicAdd(&g_cnt[recv[e] + 1], 1);
}

// register-resident vectorized single-CTA scan: 1024 thr x 28 elems (int4 x 7)
#define SC_T 1024
#define SC_V 7
__global__ void __launch_bounds__(SC_T) scan_offsets() {
    __shared__ int wsum[32];
    const int t = threadIdx.x, lane = t & 31, wid = t >> 5;
    const int base = t * (SC_V * 4);
    int v[SC_V * 4];
#pragma unroll
    for (int i = 0; i < SC_V; i++) {
        int idx = base + i * 4;
        if (idx + 3 <= NODES) {
            int4 u = *(const int4*)&g_cnt[idx];
            v[4 * i] = u.x; v[4 * i + 1] = u.y; v[4 * i + 2] = u.z; v[4 * i + 3] = u.w;
        } else {
#pragma unroll
            for (int k = 0; k < 4; k++) {
                int id = idx + k;
                v[4 * i + k] = (id <= NODES) ? g_cnt[id] : 0;
            }
        }
    }
#pragma unroll
    for (int i = 1; i < SC_V * 4; i++) v[i] += v[i - 1];
    const int mytot = v[SC_V * 4 - 1];
    int inc = mytot;
#pragma unroll
    for (int d = 1; d < 32; d <<= 1) {
        int n = __shfl_up_sync(0xffffffffu, inc, d);
        if (lane >= d) inc += n;
    }
    if (lane == 31) wsum[wid] = inc;
    __syncthreads();
    if (wid == 0) {
        int s = wsum[lane];
#pragma unroll
        for (int d = 1; d < 32; d <<= 1) {
            int n = __shfl_up_sync(0xffffffffu, s, d);
            if (lane >= d) s += n;
        }
        wsum[lane] = s;
    }
    __syncthreads();
    const int off = (wid > 0 ? wsum[wid - 1] : 0) + (inc - mytot);
#pragma unroll
    for (int i = 0; i < SC_V; i++) {
        int idx = base + i * 4;
        if (idx + 3 <= NODES) {
            int4 u = make_int4(v[4 * i] + off, v[4 * i + 1] + off,
                               v[4 * i + 2] + off, v[4 * i + 3] + off);
            *(int4*)&g_cnt[idx] = u;
        } else {
#pragma unroll
            for (int k = 0; k < 4; k++) {
                int id = idx + k;
                if (id <= NODES) g_cnt[id] = v[4 * i + k] + off;
            }
        }
    }
}

__global__ void scatter_csr(const int* __restrict__ send,
                            const int* __restrict__ recv) {
    int e = blockIdx.x * blockDim.x + threadIdx.x;
    if (e >= EDGES) return;
    int r = recv[e];
    int pos = g_cnt[r] + atomicAdd(&g_fill[r], 1);
    g_esend[pos] = send[e];
}

// =================== fused node attention + aggregation =====================
// Warp per node; K/V/Q all fp16 (L2-resident); fp32 math. Node range [base, base+cnt).
__device__ __forceinline__ void ld16h(const __half* p, float* f) {
    uint4 u0 = *(const uint4*)p;
    uint4 u1 = *(const uint4*)(p + 8);
    const __half2* h0 = (const __half2*)&u0;
    const __half2* h1 = (const __half2*)&u1;
#pragma unroll
    for (int i = 0; i < 4; i++) {
        float2 a = __half22float2(h0[i]);
        f[2 * i] = a.x; f[2 * i + 1] = a.y;
        float2 b = __half22float2(h1[i]);
        f[8 + 2 * i] = b.x; f[8 + 2 * i + 1] = b.y;
    }
}

__global__ void __launch_bounds__(256) node_attn_agg(int nodeBase, int nodeCnt) {
    int gw = (blockIdx.x * blockDim.x + threadIdx.x) >> 5;
    if (gw >= nodeCnt) return;
    const int lane = threadIdx.x & 31;
    const int r = nodeBase + gw;

    float q[16];
    ld16h(&g_KVQ[(size_t)r * NKVQ + 1024 + lane * 16], q);

    const int beg = g_cnt[r], end = g_cnt[r + 1];
    float denom = 0.0f;
    float a[16];
#pragma unroll
    for (int i = 0; i < 16; i++) a[i] = 0.0f;

    int j = beg;
    for (; j + 1 < end; j += 2) {
        int s0 = g_esend[j], s1 = g_esend[j + 1];
        const __half* b0 = &g_KVQ[(size_t)s0 * NKVQ + lane * 16];
        const __half* b1 = &g_KVQ[(size_t)s1 * NKVQ + lane * 16];
        float k0[16], v0[16], k1[16], v1[16];
        ld16h(b0, k0); ld16h(b1, k1);
        ld16h(b0 + 512, v0); ld16h(b1 + 512, v1);

        float d0 = 0.f, d1 = 0.f;
#pragma unroll
        for (int i = 0; i < 16; i++) { d0 += q[i] * k0[i]; d1 += q[i] * k1[i]; }
        d0 += __shfl_xor_sync(0xffffffffu, d0, 1);
        d1 += __shfl_xor_sync(0xffffffffu, d1, 1);
        d0 += __shfl_xor_sync(0xffffffffu, d0, 2);
        d1 += __shfl_xor_sync(0xffffffffu, d1, 2);
        float w0 = __expf(d0 * 0.125f);
        float w1 = __expf(d1 * 0.125f);
        denom += w0 + w1;
#pragma unroll
        for (int i = 0; i < 16; i++) a[i] += w0 * v0[i] + w1 * v1[i];
    }
    if (j < end) {
        int s = g_esend[j];
        const __half* b = &g_KVQ[(size_t)s * NKVQ + lane * 16];
        float k[16], v[16];
        ld16h(b, k); ld16h(b + 512, v);
        float d = 0.f;
#pragma unroll
        for (int i = 0; i < 16; i++) d += q[i] * k[i];
        d += __shfl_xor_sync(0xffffffffu, d, 1);
        d += __shfl_xor_sync(0xffffffffu, d, 2);
        float w = __expf(d * 0.125f);
        denom += w;
#pragma unroll
        for (int i = 0; i < 16; i++) a[i] += w * v[i];
    }

    float inv = (denom > 0.0f) ? 1.0f / denom : 0.0f;
    __half2 hp[8];
#pragma unroll
    for (int i = 0; i < 8; i++)
        hp[i] = __floats2half2_rn(a[2 * i] * inv, a[2 * i + 1] * inv);
    ((uint4*)&g_GF[(size_t)r * DIM + lane * 16])[0] = ((const uint4*)hp)[0];
    ((uint4*)&g_GF[(size_t)r * DIM + lane * 16])[1] = ((const uint4*)hp)[1];
}

// ---------------------------------------------------------------------------
extern "C" void kernel_launch(void* const* d_in, const int* in_sizes, int n_in,
                              void* d_out, int out_size) {
    const float* x   = (const float*)d_in[0];
    const int*  eidx = (const int*)  d_in[1];
    const float* Wk  = (const float*)d_in[2];
    const float* bk  = (const float*)d_in[3];
    const float* Wq  = (const float*)d_in[4];
    const float* bq  = (const float*)d_in[5];
    const float* Wv  = (const float*)d_in[6];
    const float* bv  = (const float*)d_in[7];
    const float* Wff = (const float*)d_in[8];
    const float* bff = (const float*)d_in[9];
    float* out = (float*)d_out;

    const int* send = eidx;
    const int* recv = eidx + EDGES;

    float* biasp;
    __half *XF, *GF, *KVQ, *WT;
    cudaGetSymbolAddress((void**)&biasp, g_bias);
    cudaGetSymbolAddress((void**)&XF,  g_XF);
    cudaGetSymbolAddress((void**)&GF,  g_GF);
    cudaGetSymbolAddress((void**)&KVQ, g_KVQ);
    cudaGetSymbolAddress((void**)&WT,  g_WT);

    cudaFuncSetAttribute((const void*)gemm_f16<true>,
        cudaFuncAttributeMaxDynamicSharedMemorySize, SMEM_G);
    cudaFuncSetAttribute((const void*)gemm_f16<false>,
        cudaFuncAttributeMaxDynamicSharedMemorySize, SMEM_G);

    static cudaStream_t s2 = nullptr;
    static cudaEvent_t evFork = nullptr, evJoin = nullptr, evA0 = nullptr,
                       evF0 = nullptr;
    if (s2 == nullptr) {
        cudaStreamCreateWithFlags(&s2, cudaStreamNonBlocking);
        cudaEventCreateWithFlags(&evFork, cudaEventDisableTiming);
        cudaEventCreateWithFlags(&evJoin, cudaEventDisableTiming);
        cudaEventCreateWithFlags(&evA0, cudaEventDisableTiming);
        cudaEventCreateWithFlags(&evF0, cudaEventDisableTiming);
    }

    // fused prep: x cast + weight transposes + CSR zero + bias concat
    prep_all<<<CTA_ALL, 256>>>(x, Wk, Wv, Wq, Wff, bk, bq, bv);

    // fork: CSR build on side stream, overlapped with the KVQ GEMM
    cudaEventRecord(evFork, 0);
    cudaStreamWaitEvent(s2, evFork, 0);
    hist_recv<<<(EDGES + 255) / 256, 256, 0, s2>>>(recv);
    scan_offsets<<<1, SC_T, 0, s2>>>();
    scatter_csr<<<(EDGES + 255) / 256, 256, 0, s2>>>(send, recv);
    cudaEventRecord(evJoin, s2);

    // fused K|V|Q GEMM: 1-term, fp16 out, N=1536 (independent of CSR)
    dim3 gkvq(NKVQ / BN, (NODES + BM - 1) / BM);   // (6, 196)
    gemm_f16<true><<<gkvq, 256, SMEM_G>>>(XF, WT, biasp, KVQ, NODES, NKVQ);

    // join: attention needs both GEMM (stream0 order) and CSR (event)
    cudaStreamWaitEvent(0, evJoin, 0);

    // ---- pipelined attention + FF over node halves ----
    node_attn_agg<<<(HALF1 * 32 + 255) / 256, 256>>>(0, HALF1);
    cudaEventRecord(evA0, 0);
    node_attn_agg<<<(HALF2 * 32 + 255) / 256, 256>>>(HALF1, HALF2);

    cudaStreamWaitEvent(s2, evA0, 0);
    dim3 gff0(DIM / BN, (HALF1 + BM - 1) / BM);    // (2, 98)
    gemm_f16<false><<<gff0, 256, SMEM_G, s2>>>(GF, WT + 3 * DIM * DIM, bff,
                                               out, HALF1, DIM);
    cudaEventRecord(evF0, s2);

    dim3 gff1(DIM / BN, (HALF2 + BM - 1) / BM);    // (2, 98)
    gemm_f16<false><<<gff1, 256, SMEM_G>>>(GF + (size_t)HALF1 * DIM,
                                           WT + 3 * DIM * DIM, bff,
                                           out + (size_t)HALF1 * DIM,
                                           HALF2, DIM);
    cudaStreamWaitEvent(0, evF0, 0);
}

// round 17
// speedup vs baseline: 1.0714x; 1.0050x over previous
#include <cuda_runtime.h>
#include <cuda_fp16.h>
#include <cstdint>

#define NODES 25000
#define EDGES 150000
#define DIM   512
#define NKVQ  1536
#define HEADS 8
#define HALF1 12500
#define HALF2 (NODES - HALF1)

// ---------------- scratch (device globals) ----------------
// weight slots (transposed [N][K] fp16): 0=Wk, 1=Wv, 2=Wq, 3=Wff
__device__ __align__(256) __half g_WT[4 * DIM * DIM];
__device__ __align__(256) __half g_KVQ[NODES * NKVQ];   // [node][K|V|Q] fp16
__device__ __align__(256) __half g_XF[NODES * DIM];     // x as fp16
__device__ __align__(256) __half g_GF[NODES * DIM];     // agg as fp16
__device__ __align__(256) float  g_bias[NKVQ];          // [bk|bv|bq]
// CSR
__device__ __align__(16) int g_cnt[NODES + 1];
__device__ int g_fill[NODES];
__device__ int g_esend[EDGES];

// =================== helpers ===================
__device__ __forceinline__ uint32_t smem_u32(const void* p) {
    uint32_t a;
    asm("{ .reg .u64 t; cvta.to.shared.u64 t, %1; cvt.u32.u64 %0, t; }"
        : "=r"(a) : "l"(p));
    return a;
}

#define CP_ASYNC(dst, src, sz) \
    asm volatile("cp.async.cg.shared.global [%0], [%1], 16, %2;" \
                 :: "r"(dst), "l"(src), "r"(sz) : "memory")
#define CP_COMMIT() asm volatile("cp.async.commit_group;" ::: "memory")
#define CP_WAIT(n)  asm volatile("cp.async.wait_group %0;" :: "n"(n) : "memory")

#define LDMATRIX_X4(r0, r1, r2, r3, a) \
    asm volatile("ldmatrix.sync.aligned.m8n8.x4.shared.b16 {%0,%1,%2,%3}, [%4];" \
                 : "=r"(r0), "=r"(r1), "=r"(r2), "=r"(r3) : "r"(a))

#define MMA_F16(d, a0, a1, a2, a3, b0, b1)                                    \
    asm volatile("mma.sync.aligned.m16n8k16.row.col.f32.f16.f16.f32 "         \
                 "{%0,%1,%2,%3}, {%4,%5,%6,%7}, {%8,%9}, {%0,%1,%2,%3};"      \
                 : "+f"((d)[0]), "+f"((d)[1]), "+f"((d)[2]), "+f"((d)[3])     \
                 : "r"(a0), "r"(a1), "r"(a2), "r"(a3), "r"(b0), "r"(b1))

// =================== fp16 GEMM (single weight term) =========================
// C[M,N] = A_f16[M,512] @ B^T + bias. CTA 128x256, 8 warps, BK=32, 6 stages.
#define BM 128
#define BN 256
#define BK 32
#define KCHUNKS (DIM / BK)
#define PITCH 80
#define SZ_AT (128 * PITCH)            // 10240
#define SZ_BT (256 * PITCH)            // 20480
#define STAGE (SZ_AT + SZ_BT)          // 30720
#define NST 6
#define SMEM_G (NST * STAGE)           // 184320

template <bool HOUT>
__global__ void __launch_bounds__(256, 1) gemm_f16(
    const __half* __restrict__ A, const __half* __restrict__ B,
    const float* __restrict__ bias, void* __restrict__ Cv, int M, int ldc)
{
    extern __shared__ char smem[];
    const uint32_t sb = smem_u32(smem);
    const int tid = threadIdx.x, wid = tid >> 5, lane = tid & 31;
    const int warpRow = wid & 1, warpCol = wid >> 1;
    const int rowBase = blockIdx.y * BM;
    const int nBase = blockIdx.x * BN;

    const int ar0 = tid >> 1, ak0 = (tid & 1) * 2;
    const uint32_t soA0 = (uint32_t)(ar0 * PITCH + ak0 * 16);
    const uint32_t soA1 = soA0 + 16;
    const uint32_t szA  = (rowBase + ar0 < M) ? 16u : 0u;
    const size_t gA0 = (size_t)(rowBase + ar0) * DIM + ak0 * 8;
    const size_t gA1 = gA0 + 8;

    uint32_t soB[4]; size_t gB[4];
#pragma unroll
    for (int i = 0; i < 4; i++) {
        int idx = i * 256 + tid;
        int br = idx >> 2, bk4 = idx & 3;
        soB[i] = (uint32_t)(br * PITCH + bk4 * 16);
        gB[i] = (size_t)(nBase + br) * DIM + bk4 * 8;
    }

    const uint32_t aOff = (uint32_t)((warpRow * 64 + (lane & 7) + ((lane >> 3) & 1) * 8) * PITCH
                                     + (lane >> 4) * 16);
    const uint32_t bOff = (uint32_t)((warpCol * 64 + (lane >> 4) * 8 + (lane & 7)) * PITCH
                                     + ((lane >> 3) & 1) * 16);

    float acc[4][8][4];
#pragma unroll
    for (int f = 0; f < 4; f++)
#pragma unroll
        for (int g = 0; g < 8; g++)
#pragma unroll
            for (int i = 0; i < 4; i++) acc[f][g][i] = 0.0f;

    auto load_stage = [&](int chunk, int buf) {
        const int k0 = chunk * BK;
        const uint32_t st = sb + (uint32_t)buf * STAGE;
        CP_ASYNC(st + soA0, A + gA0 + k0, szA);
        CP_ASYNC(st + soA1, A + gA1 + k0, szA);
#pragma unroll
        for (int i = 0; i < 4; i++)
            CP_ASYNC(st + SZ_AT + soB[i], B + gB[i] + k0, 16u);
        CP_COMMIT();
    };

#pragma unroll
    for (int s = 0; s < NST - 1; s++) load_stage(s, s);

    int buf = 0;
    for (int c = 0; c < KCHUNKS; c++) {
        int n = KCHUNKS - 1 - c; if (n > NST - 2) n = NST - 2;
        switch (n) {
            case 0: CP_WAIT(0); break;
            case 1: CP_WAIT(1); break;
            case 2: CP_WAIT(2); break;
            case 3: CP_WAIT(3); break;
            default: CP_WAIT(4); break;
        }
        __syncthreads();

        if (c + NST - 1 < KCHUNKS) {
            int nb = buf + NST - 1; if (nb >= NST) nb -= NST;
            load_stage(c + NST - 1, nb);
        }

        const uint32_t st = sb + (uint32_t)buf * STAGE;
#pragma unroll
        for (int ks = 0; ks < 2; ks++) {
            const uint32_t kb = (uint32_t)(ks * 32);
            uint32_t aF[4][4], bF[8][2];
#pragma unroll
            for (int f = 0; f < 4; f++)
                LDMATRIX_X4(aF[f][0], aF[f][1], aF[f][2], aF[f][3],
                            st + aOff + (uint32_t)(f * 16 * PITCH) + kb);
#pragma unroll
            for (int p = 0; p < 4; p++)
                LDMATRIX_X4(bF[2 * p][0], bF[2 * p][1], bF[2 * p + 1][0], bF[2 * p + 1][1],
                            st + SZ_AT + bOff + (uint32_t)(p * 16 * PITCH) + kb);
#pragma unroll
            for (int f = 0; f < 4; f++)
#pragma unroll
                for (int g = 0; g < 8; g++)
                    MMA_F16(acc[f][g], aF[f][0], aF[f][1], aF[f][2], aF[f][3],
                            bF[g][0], bF[g][1]);
        }
        buf++; if (buf >= NST) buf -= NST;
    }

#pragma unroll
    for (int f = 0; f < 4; f++) {
        const int r0 = rowBase + warpRow * 64 + f * 16 + (lane >> 2);
#pragma unroll
        for (int g = 0; g < 8; g++) {
            const int col = nBase + warpCol * 64 + g * 8 + (lane & 3) * 2;
            const float2 b = *(const float2*)(bias + col);
            if (HOUT) {
                __half* Cp = (__half*)Cv;
                if (r0 < M)
                    *(__half2*)(Cp + (size_t)r0 * ldc + col) =
                        __floats2half2_rn(acc[f][g][0] + b.x, acc[f][g][1] + b.y);
                if (r0 + 8 < M)
                    *(__half2*)(Cp + (size_t)(r0 + 8) * ldc + col) =
                        __floats2half2_rn(acc[f][g][2] + b.x, acc[f][g][3] + b.y);
            } else {
                float* Cp = (float*)Cv;
                if (r0 < M)
                    *(float2*)(Cp + (size_t)r0 * ldc + col) =
                        make_float2(acc[f][g][0] + b.x, acc[f][g][1] + b.y);
                if (r0 + 8 < M)
                    *(float2*)(Cp + (size_t)(r0 + 8) * ldc + col) =
                        make_float2(acc[f][g][2] + b.x, acc[f][g][3] + b.y);
            }
        }
    }
}

// ======== fused prep: x cast + 4x weight transpose + csr zero + bias ========
#define CTA_CAST 6250
#define CTA_TR   1024
#define CTA_ALL  (CTA_CAST + CTA_TR + 100)

__global__ void __launch_bounds__(256) prep_all(
    const float* __restrict__ x,
    const float* __restrict__ wk, const float* __restrict__ wv,
    const float* __restrict__ wq, const float* __restrict__ wff,
    const float* __restrict__ bk, const float* __restrict__ bq,
    const float* __restrict__ bv)
{
    __shared__ float t[32][33];
    const int cta = blockIdx.x, tid = threadIdx.x;

    if (cta < CTA_CAST) {
        int i = cta * 256 + tid;
        float4 v0 = ((const float4*)x)[2 * i];
        float4 v1 = ((const float4*)x)[2 * i + 1];
        __half2 h[4];
        h[0] = __floats2half2_rn(v0.x, v0.y);
        h[1] = __floats2half2_rn(v0.z, v0.w);
        h[2] = __floats2half2_rn(v1.x, v1.y);
        h[3] = __floats2half2_rn(v1.z, v1.w);
        ((uint4*)g_XF)[i] = *(const uint4*)h;
    } else if (cta < CTA_CAST + CTA_TR) {
        const int tr = cta - CTA_CAST;
        const int z = tr >> 8, rem = tr & 255;
        const float* in = (z == 0) ? wk : (z == 1) ? wv : (z == 2) ? wq : wff;
        __half* oh = g_WT + (size_t)z * DIM * DIM;
        const int bx = (rem & 15) * 32, by = (rem >> 4) * 32;
        const int tx = tid & 31, ty = tid >> 5;
#pragma unroll
        for (int j = 0; j < 32; j += 8)
            t[ty + j][tx] = in[(size_t)(by + ty + j) * DIM + bx + tx];
        __syncthreads();
#pragma unroll
        for (int j = 0; j < 32; j += 8)
            oh[(size_t)(bx + ty + j) * DIM + by + tx] =
                __float2half_rn(t[tx][ty + j]);
    } else {
        int i = (cta - CTA_CAST - CTA_TR) * 256 + tid;
        if (i <= NODES) g_cnt[i] = 0;
        if (i < NODES)  g_fill[i] = 0;
        if (i < DIM) {
            g_bias[i] = bk[i];
            g_bias[DIM + i] = bv[i];
            g_bias[2 * DIM + i] = bq[i];
        }
    }
}

// =================== CSR build ===================
__global__ void hist_recv(const int* __restrict__ recv) {
    int e = blockIdx.x * blockDim.x + threadIdx.x;
    if (e < EDGES) atomicAdd(&g_cnt[recv[e] + 1], 1);
}

#define SC_T 1024
#define SC_V 7
__global__ void __launch_bounds__(SC_T) scan_offsets() {
    __shared__ int wsum[32];
    const int t = threadIdx.x, lane = t & 31, wid = t >> 5;
    const int base = t * (SC_V * 4);
    int v[SC_V * 4];
#pragma unroll
    for (int i = 0; i < SC_V; i++) {
        int idx = base + i * 4;
        if (idx + 3 <= NODES) {
            int4 u = *(const int4*)&g_cnt[idx];
            v[4 * i] = u.x; v[4 * i + 1] = u.y; v[4 * i + 2] = u.z; v[4 * i + 3] = u.w;
        } else {
#pragma unroll
            for (int k = 0; k < 4; k++) {
                int id = idx + k;
                v[4 * i + k] = (id <= NODES) ? g_cnt[id] : 0;
            }
        }
    }
#pragma unroll
    for (int i = 1; i < SC_V * 4; i++) v[i] += v[i - 1];
    const int mytot = v[SC_V * 4 - 1];
    int inc = mytot;
#pragma unroll
    for (int d = 1; d < 32; d <<= 1) {
        int n = __shfl_up_sync(0xffffffffu, inc, d);
        if (lane >= d) inc += n;
    }
    if (lane == 31) wsum[wid] = inc;
    __syncthreads();
    if (wid == 0) {
        int s = wsum[lane];
#pragma unroll
        for (int d = 1; d < 32; d <<= 1) {
            int n = __shfl_up_sync(0xffffffffu, s, d);
            if (lane >= d) s += n;
        }
        wsum[lane] = s;
    }
    __syncthreads();
    const int off = (wid > 0 ? wsum[wid - 1] : 0) + (inc - mytot);
#pragma unroll
    for (int i = 0; i < SC_V; i++) {
        int idx = base + i * 4;
        if (idx + 3 <= NODES) {
            int4 u = make_int4(v[4 * i] + off, v[4 * i + 1] + off,
                               v[4 * i + 2] + off, v[4 * i + 3] + off);
            *(int4*)&g_cnt[idx] = u;
        } else {
#pragma unroll
            for (int k = 0; k < 4; k++) {
                int id = idx + k;
                if (id <= NODES) g_cnt[id] = v[4 * i + k] + off;
            }
        }
    }
}

__global__ void scatter_csr(const int* __restrict__ send,
                            const int* __restrict__ recv) {
    int e = blockIdx.x * blockDim.x + threadIdx.x;
    if (e >= EDGES) return;
    int r = recv[e];
    int pos = g_cnt[r] + atomicAdd(&g_fill[r], 1);
    g_esend[pos] = send[e];
}

// =================== fused node attention + aggregation =====================
// Warp per node; sender indices preloaded lane-parallel (one coalesced LDG),
// broadcast via shuffle -> removes dependent index load from the loop.
__device__ __forceinline__ void ld16h(const __half* p, float* f) {
    uint4 u0 = *(const uint4*)p;
    uint4 u1 = *(const uint4*)(p + 8);
    const __half2* h0 = (const __half2*)&u0;
    const __half2* h1 = (const __half2*)&u1;
#pragma unroll
    for (int i = 0; i < 4; i++) {
        float2 a = __half22float2(h0[i]);
        f[2 * i] = a.x; f[2 * i + 1] = a.y;
        float2 b = __half22float2(h1[i]);
        f[8 + 2 * i] = b.x; f[8 + 2 * i + 1] = b.y;
    }
}

__global__ void __launch_bounds__(256) node_attn_agg(int nodeBase, int nodeCnt) {
    int gw = (blockIdx.x * blockDim.x + threadIdx.x) >> 5;
    if (gw >= nodeCnt) return;
    const int lane = threadIdx.x & 31;
    const int r = nodeBase + gw;

    float q[16];
    ld16h(&g_KVQ[(size_t)r * NKVQ + 1024 + lane * 16], q);

    const int beg = g_cnt[r], end = g_cnt[r + 1];
    const int deg = end - beg;
    // lane-parallel preload of up to 32 sender indices (one transaction)
    const int myS = (lane < deg) ? g_esend[beg + lane] : 0;

    float denom = 0.0f;
    float a[16];
#pragma unroll
    for (int i = 0; i < 16; i++) a[i] = 0.0f;

    const int nPre = (deg < 32) ? deg : 32;
    int j = 0;
    for (; j + 1 < nPre; j += 2) {
        int s0 = __shfl_sync(0xffffffffu, myS, j);
        int s1 = __shfl_sync(0xffffffffu, myS, j + 1);
        const __half* b0 = &g_KVQ[(size_t)s0 * NKVQ + lane * 16];
        const __half* b1 = &g_KVQ[(size_t)s1 * NKVQ + lane * 16];
        float k0[16], v0[16], k1[16], v1[16];
        ld16h(b0, k0); ld16h(b1, k1);
        ld16h(b0 + 512, v0); ld16h(b1 + 512, v1);

        float d0 = 0.f, d1 = 0.f;
#pragma unroll
        for (int i = 0; i < 16; i++) { d0 += q[i] * k0[i]; d1 += q[i] * k1[i]; }
        d0 += __shfl_xor_sync(0xffffffffu, d0, 1);
        d1 += __shfl_xor_sync(0xffffffffu, d1, 1);
        d0 += __shfl_xor_sync(0xffffffffu, d0, 2);
        d1 += __shfl_xor_sync(0xffffffffu, d1, 2);
        float w0 = __expf(d0 * 0.125f);
        float w1 = __expf(d1 * 0.125f);
        denom += w0 + w1;
#pragma unroll
        for (int i = 0; i < 16; i++) a[i] += w0 * v0[i] + w1 * v1[i];
    }
    if (j < nPre) {
        int s = __shfl_sync(0xffffffffu, myS, j);
        const __half* b = &g_KVQ[(size_t)s * NKVQ + lane * 16];
        float k[16], v[16];
        ld16h(b, k); ld16h(b + 512, v);
        float d = 0.f;
#pragma unroll
        for (int i = 0; i < 16; i++) d += q[i] * k[i];
        d += __shfl_xor_sync(0xffffffffu, d, 1);
        d += __shfl_xor_sync(0xffffffffu, d, 2);
        float w = __expf(d * 0.125f);
        denom += w;
#pragma unroll
        for (int i = 0; i < 16; i++) a[i] += w * v[i];
        j++;
    }
    // rare tail: degree > 32 (direct loads, same order)
    for (int t = 32; t < deg; t++) {
        int s = g_esend[beg + t];
        const __half* b = &g_KVQ[(size_t)s * NKVQ + lane * 16];
        float k[16], v[16];
        ld16h(b, k); ld16h(b + 512, v);
        float d = 0.f;
#pragma unroll
        for (int i = 0; i < 16; i++) d += q[i] * k[i];
        d += __shfl_xor_sync(0xffffffffu, d, 1);
        d += __shfl_xor_sync(0xffffffffu, d, 2);
        float w = __expf(d * 0.125f);
        denom += w;
#pragma unroll
        for (int i = 0; i < 16; i++) a[i] += w * v[i];
    }

    float inv = (denom > 0.0f) ? 1.0f / denom : 0.0f;
    __half2 hp[8];
#pragma unroll
    for (int i = 0; i < 8; i++)
        hp[i] = __floats2half2_rn(a[2 * i] * inv, a[2 * i + 1] * inv);
    ((uint4*)&g_GF[(size_t)r * DIM + lane * 16])[0] = ((const uint4*)hp)[0];
    ((uint4*)&g_GF[(size_t)r * DIM + lane * 16])[1] = ((const uint4*)hp)[1];
}

// ---------------------------------------------------------------------------
extern "C" void kernel_launch(void* const* d_in, const int* in_sizes, int n_in,
                              void* d_out, int out_size) {
    const float* x   = (const float*)d_in[0];
    const int*  eidx = (const int*)  d_in[1];
    const float* Wk  = (const float*)d_in[2];
    const float* bk  = (const float*)d_in[3];
    const float* Wq  = (const float*)d_in[4];
    const float* bq  = (const float*)d_in[5];
    const float* Wv  = (const float*)d_in[6];
    const float* bv  = (const float*)d_in[7];
    const float* Wff = (const float*)d_in[8];
    const float* bff = (const float*)d_in[9];
    float* out = (float*)d_out;

    const int* send = eidx;
    const int* recv = eidx + EDGES;

    float* biasp;
    __half *XF, *GF, *KVQ, *WT;
    cudaGetSymbolAddress((void**)&biasp, g_bias);
    cudaGetSymbolAddress((void**)&XF,  g_XF);
    cudaGetSymbolAddress((void**)&GF,  g_GF);
    cudaGetSymbolAddress((void**)&KVQ, g_KVQ);
    cudaGetSymbolAddress((void**)&WT,  g_WT);

    cudaFuncSetAttribute((const void*)gemm_f16<true>,
        cudaFuncAttributeMaxDynamicSharedMemorySize, SMEM_G);
    cudaFuncSetAttribute((const void*)gemm_f16<false>,
        cudaFuncAttributeMaxDynamicSharedMemorySize, SMEM_G);

    static cudaStream_t s2 = nullptr;
    static cudaEvent_t evFork = nullptr, evJoin = nullptr, evA0 = nullptr,
                       evF0 = nullptr;
    if (s2 == nullptr) {
        cudaStreamCreateWithFlags(&s2, cudaStreamNonBlocking);
        cudaEventCreateWithFlags(&evFork, cudaEventDisableTiming);
        cudaEventCreateWithFlags(&evJoin, cudaEventDisableTiming);
        cudaEventCreateWithFlags(&evA0, cudaEventDisableTiming);
        cudaEventCreateWithFlags(&evF0, cudaEventDisableTiming);
    }

    // fused prep: x cast + weight transposes + CSR zero + bias concat
    prep_all<<<CTA_ALL, 256>>>(x, Wk, Wv, Wq, Wff, bk, bq, bv);

    // fork: CSR build on side stream, overlapped with the KVQ GEMM
    cudaEventRecord(evFork, 0);
    cudaStreamWaitEvent(s2, evFork, 0);
    hist_recv<<<(EDGES + 255) / 256, 256, 0, s2>>>(recv);
    scan_offsets<<<1, SC_T, 0, s2>>>();
    scatter_csr<<<(EDGES + 255) / 256, 256, 0, s2>>>(send, recv);
    cudaEventRecord(evJoin, s2);

    // fused K|V|Q GEMM: 1-term, fp16 out, N=1536 (independent of CSR)
    dim3 gkvq(NKVQ / BN, (NODES + BM - 1) / BM);   // (6, 196)
    gemm_f16<true><<<gkvq, 256, SMEM_G>>>(XF, WT, biasp, KVQ, NODES, NKVQ);

    // join: attention needs both GEMM (stream0 order) and CSR (event)
    cudaStreamWaitEvent(0, evJoin, 0);

    // ---- pipelined attention + FF over node halves ----
    node_attn_agg<<<(HALF1 * 32 + 255) / 256, 256>>>(0, HALF1);
    cudaEventRecord(evA0, 0);
    node_attn_agg<<<(HALF2 * 32 + 255) / 256, 256>>>(HALF1, HALF2);

    cudaStreamWaitEvent(s2, evA0, 0);
    dim3 gff0(DIM / BN, (HALF1 + BM - 1) / BM);    // (2, 98)
    gemm_f16<false><<<gff0, 256, SMEM_G, s2>>>(GF, WT + 3 * DIM * DIM, bff,
                                               out, HALF1, DIM);
    cudaEventRecord(evF0, s2);

    dim3 gff1(DIM / BN, (HALF2 + BM - 1) / BM);    // (2, 98)
    gemm_f16<false><<<gff1, 256, SMEM_G>>>(GF + (size_t)HALF1 * DIM,
                                           WT + 3 * DIM * DIM, bff,
                                           out + (size_t)HALF1 * DIM,
                                           HALF2, DIM);
    cudaStreamWaitEvent(0, evF0, 0);
}